// round 15
// baseline (speedup 1.0000x reference)
#include <cuda_runtime.h>

// FilteredNoise: per-frame zero-phase FIR synthesis from real spectrum + OLA.
//   ir[n]  = (1/129)(X[0] + 2 sum_{k=1..64} X[k] cos(2pi k n / 129)),  ir symmetric
//   h[64-n] = ir[n]*win[64-n], h[64+n] = ir[n]*win[64+n]   (win = periodic Hann 129)
//   out[b, f*64 + t] += GAIN * sum_s n2[s] h[t-s]
//
// CTA = 128 threads, owns 2048 output samples (32 hop blocks) of one batch row.
// Phase A: 4 warps x 9 frames, lanes <-> IR-index pair (n, n+32), Chebyshev cos
//   recurrence, X read as float4 LDS broadcasts (k-vectorized).
// Phase B: warp -> tau in {0,16,32,48}; thread owns 16 outputs as two fused
//   8-tiles sharing one h-window + one noise load per 8-step block; R-window
//   slides via register renaming (peel + unroll-2), fma.rn.f32x2 step pairs.

#define THREADS 128
#define SXROW 68    // 17 x 16B granules (odd), k padded 65->68 (aligned float4)
#define SHROW 172   // 43 granules (odd): 16 front pads | h[0..128] | 23 back pads
#define SNROW 68
#define HPAD  16

typedef unsigned long long u64;

__device__ __forceinline__ u64 pk2(float lo, float hi) {
    u64 r; asm("mov.b64 %0, {%1, %2};" : "=l"(r) : "f"(lo), "f"(hi)); return r;
}
__device__ __forceinline__ void upk2(u64 v, float& lo, float& hi) {
    asm("mov.b64 {%0, %1}, %2;" : "=f"(lo), "=f"(hi) : "l"(v));
}
__device__ __forceinline__ float hi2(u64 v) {
    float lo, hi; upk2(v, lo, hi); return hi;
}
__device__ __forceinline__ void ffma2(u64& d, u64 a, u64 b) {
    asm("fma.rn.f32x2 %0, %1, %2, %0;" : "+l"(d) : "l"(a), "l"(b));
}

// one 8-step MAC over both 8-output tiles: 2 LDS.128 noise, 64 ffma2
#define MAC(sb_, R_) do {                                                     \
    ulonglong2 nn0 = *(const ulonglong2*)(nrow + (sb_));                      \
    ulonglong2 nn1 = *(const ulonglong2*)(nrow + (sb_) + 4);                  \
    u64 nA[4] = {nn0.x, nn0.y, nn1.x, nn1.y};                                 \
    _Pragma("unroll") for (int u = 0; u < 4; ++u) {                           \
        _Pragma("unroll") for (int i = 0; i < 8; ++i)                         \
            ffma2(accA[i], nA[u], R_[i - 2*u + 6]);                           \
        _Pragma("unroll") for (int i = 0; i < 8; ++i)                         \
            ffma2(accB[i], nA[u], R_[i - 2*u + 14]);                          \
    }                                                                         \
} while (0)

// slide window 8 left (Rout[8..21] = Rin[0..13] by renaming), then MAC
#define BSTEP(Rin, Rout) do {                                                 \
    x -= 8;                                                                   \
    float4 La = *(const float4*)(hrow + x - 8);                               \
    float4 Lb = *(const float4*)(hrow + x - 4);                               \
    float L[8] = {La.x, La.y, La.z, La.w, Lb.x, Lb.y, Lb.z, Lb.w};            \
    _Pragma("unroll") for (int idx = 0; idx < 6; ++idx)                       \
        Rout[idx] = pk2(L[idx + 2], L[idx + 1]);                              \
    Rout[6] = pk2(h_top, L[7]);                                               \
    Rout[7] = pk2(hi2(Rin[0]), h_top);                                        \
    _Pragma("unroll") for (int idx = 8; idx < 22; ++idx)                      \
        Rout[idx] = Rin[idx - 8];                                             \
    h_top = L[0];                                                             \
    MAC(sb, Rout);                                                            \
    sb += 8;                                                                  \
} while (0)

__global__ __launch_bounds__(THREADS, 4)
void filtered_noise_kernel(const float* __restrict__ filt,
                           const float* __restrict__ noise,
                           float* __restrict__ out,
                           int F, long outlen)
{
    __shared__ __align__(16) float sX[36 * SXROW];   // scaled X (X0 pre-halved)
    __shared__ __align__(16) float sH[36 * SHROW];
    __shared__ __align__(16) float sN[34 * SNROW];   // n2 = 2*noise-1

    const int tid  = threadIdx.x;
    const int w    = tid >> 5;
    const int lane = tid & 31;
    const int g    = blockIdx.x;
    const int b    = blockIdx.y;
    const long base_f = (long)g * 32 - 2;

    const float* fb = filt  + (long)b * F * 65;
    const float* nb = noise + (long)b * F * 64;

    // ---- fills ----
    for (int i = tid; i < 36 * SXROW; i += THREADS) {
        int lf = i / SXROW, k = i - lf * SXROW;
        long f = base_f + lf;
        float v = 0.0f;
        if (lf < 34 && k < 65 && f >= 0 && f < F) v = fb[f * 65 + k];
        sX[i] = (k == 0) ? 0.5f * v : v;      // fold the k=0 half-weight
    }
    for (int i = tid; i < 34 * 16; i += THREADS) {
        int lf = i >> 4, j = i & 15;
        long f = base_f + lf;
        float4 v = make_float4(0.5f, 0.5f, 0.5f, 0.5f);
        if (f >= 0 && f < F) v = ((const float4*)(nb + f * 64))[j];
        *(float4*)(sN + lf * SNROW + 4 * j) =
            make_float4(2.0f * v.x - 1.0f, 2.0f * v.y - 1.0f,
                        2.0f * v.z - 1.0f, 2.0f * v.w - 1.0f);
    }
    for (int i = tid; i < 36 * 39; i += THREADS) {   // zero sH pads
        int lf = i / 39, j = i - lf * 39;
        sH[lf * SHROW + (j < 16 ? j : j + 129)] = 0.0f;
    }
    __syncthreads();

    // ---- Phase A: IR synthesis, 4 warps x 9 frames, float4 k-broadcasts ----
    {
        const int n0 = lane + 1, n1 = lane + 33;
        const float th0 = cospif((float)(2 * n0) / 129.0f);
        const float th1 = cospif((float)(2 * n1) / 129.0f);
        const float k20 = 2.0f * th0, k21 = 2.0f * th1;
        float c0 = 1.0f, c1 = 1.0f, p0 = th0, p1 = th1;   // cos(k t), cos((k-1)t)

        const int fs = 9 * w;                 // frames fs..fs+8 (rows 34,35: X=0)
        const float* xp = sX + fs * SXROW;
        u64 acc[9];
        #pragma unroll
        for (int j = 0; j < 9; ++j) acc[j] = 0ull;

        for (int k4 = 0; k4 < 17; ++k4) {     // k = 0..67 (65..67 are zero pads)
            float4 xv[9];
            #pragma unroll
            for (int j = 0; j < 9; ++j)
                xv[j] = *(const float4*)(xp + j * SXROW + 4 * k4);
            #pragma unroll
            for (int e = 0; e < 4; ++e) {
                u64 cc = pk2(c0, c1);
                #pragma unroll
                for (int j = 0; j < 9; ++j) {
                    float xe = (e == 0) ? xv[j].x : (e == 1) ? xv[j].y
                             : (e == 2) ? xv[j].z : xv[j].w;
                    ffma2(acc[j], pk2(xe, xe), cc);
                }
                float t0n = fmaf(k20, c0, -p0); p0 = c0; c0 = t0n;
                float t1n = fmaf(k21, c1, -p1); p1 = c1; c1 = t1n;
            }
        }
        const float S = 0.02f / 129.0f;       // GAIN * 2 / 129
        float w1a = (0.5f - 0.5f * cospif((float)(2 * (64 - n0)) / 129.0f)) * S;
        float w2a = (0.5f - 0.5f * cospif((float)(2 * (64 + n0)) / 129.0f)) * S;
        float w1b = (0.5f - 0.5f * cospif((float)(2 * (64 - n1)) / 129.0f)) * S;
        float w2b = (0.5f - 0.5f * cospif((float)(2 * (64 + n1)) / 129.0f)) * S;
        #pragma unroll
        for (int j = 0; j < 9; ++j) {
            float i0, i1; upk2(acc[j], i0, i1);
            float* hr = sH + (fs + j) * SHROW + HPAD;
            hr[64 - n0] = i0 * w1a;  hr[64 + n0] = i0 * w2a;
            hr[64 - n1] = i1 * w1b;  hr[64 + n1] = i1 * w2b;
        }
    }
    // n = 0 leftover: h[64] = win[64]*S * (0.5 X0 + sum_k Xk)   (X0 pre-halved)
    if (tid < 34) {
        const float* xr = sX + tid * SXROW;
        float s0 = xr[0], s1 = 0.0f, s2 = 0.0f, s3 = 0.0f;
        #pragma unroll 4
        for (int k = 1; k < 65; k += 4) {
            s0 += xr[k]; s1 += xr[k + 1]; s2 += xr[k + 2]; s3 += xr[k + 3];
        }
        const float win64s = (0.5f - 0.5f * cospif(128.0f / 129.0f)) * (0.02f / 129.0f);
        sH[tid * SHROW + HPAD + 64] = (s0 + s1 + s2 + s3) * win64s;
    }
    __syncthreads();

    // ---- Phase B: fused two-tile FIR conv + OLA ----
    const int tau = w << 4;        // 0,16,32,48
    const int hb  = lane;          // local hop block

    u64 accA[8], accB[8];          // tiles [tau, tau+8) and [tau+8, tau+16)
    #pragma unroll
    for (int i = 0; i < 8; ++i) { accA[i] = 0ull; accB[i] = 0ull; }

    #pragma unroll
    for (int d = 0; d < 3; ++d) {  // frame offset: f = hopblock - d
        long fglob = (long)g * 32 + hb - d;
        if (fglob < 0 || fglob >= F) continue;
        const int lf = hb - d + 2;
        const int t0 = tau + (d << 6);
        const int s_lo  = (d == 2) ? tau : 0;
        const int s_end = (d == 0) ? tau + 16 : 64;

        const float* hrow = sH + lf * SHROW + HPAD;   // hrow[-16..151] valid
        const float* nrow = sN + lf * SNROW;

        int x  = t0 - s_lo;        // multiple of 8
        int sb = s_lo;
        float h_top;
        u64 Ra[22], Rb[22];        // R[idx] = (h[m+1], h[m]), m = x-7+idx
        {   // prologue: build Ra for the first block, then MAC
            float hb24[24];        // h[x-8 .. x+15]
            #pragma unroll
            for (int q = 0; q < 6; ++q) {
                float4 t = *(const float4*)(hrow + x - 8 + 4 * q);
                hb24[4*q] = t.x; hb24[4*q+1] = t.y; hb24[4*q+2] = t.z; hb24[4*q+3] = t.w;
            }
            #pragma unroll
            for (int idx = 0; idx < 22; ++idx)
                Ra[idx] = pk2(hb24[idx + 2], hb24[idx + 1]);
            h_top = hb24[0];       // h[x-8] for the next slide
            MAC(sb, Ra);
            sb += 8;
        }
        while (sb + 15 < s_end) {  // even pairs: register-renamed R rotation
            BSTEP(Ra, Rb);
            BSTEP(Rb, Ra);
        }
        if (sb < s_end) {
            BSTEP(Ra, Rb);
        }
    }

    // each (g, hb, tau) tile of 16 samples owned by exactly one thread
    long p0 = (long)g * 2048 + (long)hb * 64 + tau;
    float* op = out + (long)b * outlen + p0;
    if (p0 < outlen) {
        float o[8];
        #pragma unroll
        for (int i = 0; i < 8; ++i) { float lo, hi; upk2(accA[i], lo, hi); o[i] = lo + hi; }
        reinterpret_cast<float4*>(op)[0] = make_float4(o[0], o[1], o[2], o[3]);
        reinterpret_cast<float4*>(op)[1] = make_float4(o[4], o[5], o[6], o[7]);
    }
    if (p0 + 8 < outlen) {
        float o[8];
        #pragma unroll
        for (int i = 0; i < 8; ++i) { float lo, hi; upk2(accB[i], lo, hi); o[i] = lo + hi; }
        reinterpret_cast<float4*>(op)[2] = make_float4(o[0], o[1], o[2], o[3]);
        reinterpret_cast<float4*>(op)[3] = make_float4(o[4], o[5], o[6], o[7]);
    }
}

extern "C" void kernel_launch(void* const* d_in, const int* in_sizes, int n_in,
                              void* d_out, int out_size)
{
    const float* d_filter = (const float*)d_in[0];   // [B, F, 65]
    const float* d_noise  = (const float*)d_in[1];   // [B, F, 64]
    float* d_o = (float*)d_out;                      // [B, (F-1)*64 + 192]

    const long nframes = (long)in_sizes[0] / 65;     // B*F
    const long B = ((long)out_size - 64 * nframes) / 128;
    const int  F = (int)(nframes / B);
    const long outlen = (long)(F - 1) * 64 + 192;
    const int  G = (int)((outlen + 2047) / 2048);

    dim3 grid((unsigned)G, (unsigned)B);
    filtered_noise_kernel<<<grid, THREADS>>>(d_filter, d_noise, d_o, F, outlen);
}

// round 16
// speedup vs baseline: 1.0019x; 1.0019x over previous
#include <cuda_runtime.h>

// FilteredNoise: per-frame zero-phase FIR synthesis from real spectrum + OLA.
//   ir[n]  = (1/129)(X[0] + 2 sum_{k=1..64} X[k] cos(2pi k n / 129)),  ir symmetric
//   h[64-n] = ir[n]*win[64-n], h[64+n] = ir[n]*win[64+n]   (win = periodic Hann 129)
//   out[b, f*64 + t] += GAIN * sum_s n2[s] h[t-s]
//
// CTA = 128 threads, owns 2048 output samples (32 hop blocks) of one batch row.
// Phase A: 4 warps x 9 frames, lanes <-> IR-index pair (n, n+32), Chebyshev cos
//   recurrence, X read as float4 LDS broadcasts (k-vectorized).
// Phase B: warp -> tau in {0,16,32,48}; thread owns 16 outputs as two fused
//   8-tiles sharing one h-window + one noise load per 8-step block; R-window
//   slides via register renaming (peel + unroll-2), fma.rn.f32x2 step pairs.

#define THREADS 128
#define SXROW 68    // 17 x 16B granules (odd), k padded 65->68 (aligned float4)
#define SHROW 172   // 43 granules (odd): 16 front pads | h[0..128] | 23 back pads
#define SNROW 68
#define HPAD  16

typedef unsigned long long u64;

__device__ __forceinline__ u64 pk2(float lo, float hi) {
    u64 r; asm("mov.b64 %0, {%1, %2};" : "=l"(r) : "f"(lo), "f"(hi)); return r;
}
__device__ __forceinline__ void upk2(u64 v, float& lo, float& hi) {
    asm("mov.b64 {%0, %1}, %2;" : "=f"(lo), "=f"(hi) : "l"(v));
}
__device__ __forceinline__ float hi2(u64 v) {
    float lo, hi; upk2(v, lo, hi); return hi;
}
__device__ __forceinline__ void ffma2(u64& d, u64 a, u64 b) {
    asm("fma.rn.f32x2 %0, %1, %2, %0;" : "+l"(d) : "l"(a), "l"(b));
}

// one 8-step MAC over both 8-output tiles: 2 LDS.128 noise, 64 ffma2
#define MAC(sb_, R_) do {                                                     \
    ulonglong2 nn0 = *(const ulonglong2*)(nrow + (sb_));                      \
    ulonglong2 nn1 = *(const ulonglong2*)(nrow + (sb_) + 4);                  \
    u64 nA[4] = {nn0.x, nn0.y, nn1.x, nn1.y};                                 \
    _Pragma("unroll") for (int u = 0; u < 4; ++u) {                           \
        _Pragma("unroll") for (int i = 0; i < 8; ++i)                         \
            ffma2(accA[i], nA[u], R_[i - 2*u + 6]);                           \
        _Pragma("unroll") for (int i = 0; i < 8; ++i)                         \
            ffma2(accB[i], nA[u], R_[i - 2*u + 14]);                          \
    }                                                                         \
} while (0)

// slide window 8 left (Rout[8..21] = Rin[0..13] by renaming), then MAC
#define BSTEP(Rin, Rout) do {                                                 \
    x -= 8;                                                                   \
    float4 La = *(const float4*)(hrow + x - 8);                               \
    float4 Lb = *(const float4*)(hrow + x - 4);                               \
    float L[8] = {La.x, La.y, La.z, La.w, Lb.x, Lb.y, Lb.z, Lb.w};            \
    _Pragma("unroll") for (int idx = 0; idx < 6; ++idx)                       \
        Rout[idx] = pk2(L[idx + 2], L[idx + 1]);                              \
    Rout[6] = pk2(h_top, L[7]);                                               \
    Rout[7] = pk2(hi2(Rin[0]), h_top);                                        \
    _Pragma("unroll") for (int idx = 8; idx < 22; ++idx)                      \
        Rout[idx] = Rin[idx - 8];                                             \
    h_top = L[0];                                                             \
    MAC(sb, Rout);                                                            \
    sb += 8;                                                                  \
} while (0)

__global__ __launch_bounds__(THREADS, 4)
void filtered_noise_kernel(const float* __restrict__ filt,
                           const float* __restrict__ noise,
                           float* __restrict__ out,
                           int F, long outlen)
{
    __shared__ __align__(16) float sX[36 * SXROW];   // scaled X (X0 pre-halved)
    __shared__ __align__(16) float sH[36 * SHROW];
    __shared__ __align__(16) float sN[34 * SNROW];   // n2 = 2*noise-1

    const int tid  = threadIdx.x;
    const int w    = tid >> 5;
    const int lane = tid & 31;
    const int g    = blockIdx.x;
    const int b    = blockIdx.y;
    const long base_f = (long)g * 32 - 2;

    const float* fb = filt  + (long)b * F * 65;
    const float* nb = noise + (long)b * F * 64;

    // ---- fills ----
    for (int i = tid; i < 36 * SXROW; i += THREADS) {
        int lf = i / SXROW, k = i - lf * SXROW;
        long f = base_f + lf;
        float v = 0.0f;
        if (lf < 34 && k < 65 && f >= 0 && f < F) v = fb[f * 65 + k];
        sX[i] = (k == 0) ? 0.5f * v : v;      // fold the k=0 half-weight
    }
    for (int i = tid; i < 34 * 16; i += THREADS) {
        int lf = i >> 4, j = i & 15;
        long f = base_f + lf;
        float4 v = make_float4(0.5f, 0.5f, 0.5f, 0.5f);
        if (f >= 0 && f < F) v = ((const float4*)(nb + f * 64))[j];
        *(float4*)(sN + lf * SNROW + 4 * j) =
            make_float4(2.0f * v.x - 1.0f, 2.0f * v.y - 1.0f,
                        2.0f * v.z - 1.0f, 2.0f * v.w - 1.0f);
    }
    for (int i = tid; i < 36 * 39; i += THREADS) {   // zero sH pads
        int lf = i / 39, j = i - lf * 39;
        sH[lf * SHROW + (j < 16 ? j : j + 129)] = 0.0f;
    }
    __syncthreads();

    // ---- Phase A: IR synthesis, 4 warps x 9 frames, float4 k-broadcasts ----
    {
        const int n0 = lane + 1, n1 = lane + 33;
        const float th0 = cospif((float)(2 * n0) / 129.0f);
        const float th1 = cospif((float)(2 * n1) / 129.0f);
        const float k20 = 2.0f * th0, k21 = 2.0f * th1;
        float c0 = 1.0f, c1 = 1.0f, p0 = th0, p1 = th1;   // cos(k t), cos((k-1)t)

        const int fs = 9 * w;                 // frames fs..fs+8 (rows 34,35: X=0)
        const float* xp = sX + fs * SXROW;
        u64 acc[9];
        #pragma unroll
        for (int j = 0; j < 9; ++j) acc[j] = 0ull;

        for (int k4 = 0; k4 < 17; ++k4) {     // k = 0..67 (65..67 are zero pads)
            float4 xv[9];
            #pragma unroll
            for (int j = 0; j < 9; ++j)
                xv[j] = *(const float4*)(xp + j * SXROW + 4 * k4);
            #pragma unroll
            for (int e = 0; e < 4; ++e) {
                u64 cc = pk2(c0, c1);
                #pragma unroll
                for (int j = 0; j < 9; ++j) {
                    float xe = (e == 0) ? xv[j].x : (e == 1) ? xv[j].y
                             : (e == 2) ? xv[j].z : xv[j].w;
                    ffma2(acc[j], pk2(xe, xe), cc);
                }
                float t0n = fmaf(k20, c0, -p0); p0 = c0; c0 = t0n;
                float t1n = fmaf(k21, c1, -p1); p1 = c1; c1 = t1n;
            }
        }
        const float S = 0.02f / 129.0f;       // GAIN * 2 / 129
        float w1a = (0.5f - 0.5f * cospif((float)(2 * (64 - n0)) / 129.0f)) * S;
        float w2a = (0.5f - 0.5f * cospif((float)(2 * (64 + n0)) / 129.0f)) * S;
        float w1b = (0.5f - 0.5f * cospif((float)(2 * (64 - n1)) / 129.0f)) * S;
        float w2b = (0.5f - 0.5f * cospif((float)(2 * (64 + n1)) / 129.0f)) * S;
        #pragma unroll
        for (int j = 0; j < 9; ++j) {
            float i0, i1; upk2(acc[j], i0, i1);
            float* hr = sH + (fs + j) * SHROW + HPAD;
            hr[64 - n0] = i0 * w1a;  hr[64 + n0] = i0 * w2a;
            hr[64 - n1] = i1 * w1b;  hr[64 + n1] = i1 * w2b;
        }
    }
    // n = 0 leftover: h[64] = win[64]*S * (0.5 X0 + sum_k Xk)   (X0 pre-halved)
    if (tid < 34) {
        const float* xr = sX + tid * SXROW;
        float s0 = xr[0], s1 = 0.0f, s2 = 0.0f, s3 = 0.0f;
        #pragma unroll 4
        for (int k = 1; k < 65; k += 4) {
            s0 += xr[k]; s1 += xr[k + 1]; s2 += xr[k + 2]; s3 += xr[k + 3];
        }
        const float win64s = (0.5f - 0.5f * cospif(128.0f / 129.0f)) * (0.02f / 129.0f);
        sH[tid * SHROW + HPAD + 64] = (s0 + s1 + s2 + s3) * win64s;
    }
    __syncthreads();

    // ---- Phase B: fused two-tile FIR conv + OLA ----
    const int tau = w << 4;        // 0,16,32,48
    const int hb  = lane;          // local hop block

    u64 accA[8], accB[8];          // tiles [tau, tau+8) and [tau+8, tau+16)
    #pragma unroll
    for (int i = 0; i < 8; ++i) { accA[i] = 0ull; accB[i] = 0ull; }

    #pragma unroll
    for (int d = 0; d < 3; ++d) {  // frame offset: f = hopblock - d
        long fglob = (long)g * 32 + hb - d;
        if (fglob < 0 || fglob >= F) continue;
        const int lf = hb - d + 2;
        const int t0 = tau + (d << 6);
        const int s_lo  = (d == 2) ? tau : 0;
        const int s_end = (d == 0) ? tau + 16 : 64;

        const float* hrow = sH + lf * SHROW + HPAD;   // hrow[-16..151] valid
        const float* nrow = sN + lf * SNROW;

        int x  = t0 - s_lo;        // multiple of 8
        int sb = s_lo;
        float h_top;
        u64 Ra[22], Rb[22];        // R[idx] = (h[m+1], h[m]), m = x-7+idx
        {   // prologue: build Ra for the first block, then MAC
            float hb24[24];        // h[x-8 .. x+15]
            #pragma unroll
            for (int q = 0; q < 6; ++q) {
                float4 t = *(const float4*)(hrow + x - 8 + 4 * q);
                hb24[4*q] = t.x; hb24[4*q+1] = t.y; hb24[4*q+2] = t.z; hb24[4*q+3] = t.w;
            }
            #pragma unroll
            for (int idx = 0; idx < 22; ++idx)
                Ra[idx] = pk2(hb24[idx + 2], hb24[idx + 1]);
            h_top = hb24[0];       // h[x-8] for the next slide
            MAC(sb, Ra);
            sb += 8;
        }
        while (sb + 15 < s_end) {  // even pairs: register-renamed R rotation
            BSTEP(Ra, Rb);
            BSTEP(Rb, Ra);
        }
        if (sb < s_end) {
            BSTEP(Ra, Rb);
        }
    }

    // each (g, hb, tau) tile of 16 samples owned by exactly one thread
    long p0 = (long)g * 2048 + (long)hb * 64 + tau;
    float* op = out + (long)b * outlen + p0;
    if (p0 < outlen) {
        float o[8];
        #pragma unroll
        for (int i = 0; i < 8; ++i) { float lo, hi; upk2(accA[i], lo, hi); o[i] = lo + hi; }
        reinterpret_cast<float4*>(op)[0] = make_float4(o[0], o[1], o[2], o[3]);
        reinterpret_cast<float4*>(op)[1] = make_float4(o[4], o[5], o[6], o[7]);
    }
    if (p0 + 8 < outlen) {
        float o[8];
        #pragma unroll
        for (int i = 0; i < 8; ++i) { float lo, hi; upk2(accB[i], lo, hi); o[i] = lo + hi; }
        reinterpret_cast<float4*>(op)[2] = make_float4(o[0], o[1], o[2], o[3]);
        reinterpret_cast<float4*>(op)[3] = make_float4(o[4], o[5], o[6], o[7]);
    }
}

extern "C" void kernel_launch(void* const* d_in, const int* in_sizes, int n_in,
                              void* d_out, int out_size)
{
    const float* d_filter = (const float*)d_in[0];   // [B, F, 65]
    const float* d_noise  = (const float*)d_in[1];   // [B, F, 64]
    float* d_o = (float*)d_out;                      // [B, (F-1)*64 + 192]

    const long nframes = (long)in_sizes[0] / 65;     // B*F
    const long B = ((long)out_size - 64 * nframes) / 128;
    const int  F = (int)(nframes / B);
    const long outlen = (long)(F - 1) * 64 + 192;
    const int  G = (int)((outlen + 2047) / 2048);

    dim3 grid((unsigned)G, (unsigned)B);
    filtered_noise_kernel<<<grid, THREADS>>>(d_filter, d_noise, d_o, F, outlen);
}

// round 17
// speedup vs baseline: 1.0120x; 1.0101x over previous
#include <cuda_runtime.h>

// FilteredNoise: per-frame zero-phase FIR synthesis from real spectrum + OLA.
//   ir[n]  = (1/129)(X[0] + 2 sum_{k=1..64} X[k] cos(2pi k n / 129)),  ir symmetric
//   h[64-n] = ir[n]*win[64-n], h[64+n] = ir[n]*win[64+n]   (win = periodic Hann 129)
//   out[b, f*64 + t] += GAIN * sum_s n2[s] h[t-s]
//
// CTA = 128 threads, owns 2048 output samples (32 hop blocks) of one batch row.
// Phase A: 4 warps x 9 frames, lanes <-> IR-index pair (n, n+32), Chebyshev cos
//   recurrence, X read as float4 LDS broadcasts (k-vectorized).
// Phase B: warp -> tau in {0,16,32,48}; thread owns 16 outputs as two fused
//   8-tiles sharing one h-window + one noise load per 8-step block; R-window
//   slides via register renaming (peel + unroll-2), fma.rn.f32x2 step pairs.

#define THREADS 128
#define SXROW 68    // 17 x 16B granules (odd), k padded 65->68 (aligned float4)
#define SHROW 172   // 43 granules (odd): 16 front pads | h[0..128] | 23 back pads
#define SNROW 68
#define HPAD  16

typedef unsigned long long u64;

__device__ __forceinline__ u64 pk2(float lo, float hi) {
    u64 r; asm("mov.b64 %0, {%1, %2};" : "=l"(r) : "f"(lo), "f"(hi)); return r;
}
__device__ __forceinline__ void upk2(u64 v, float& lo, float& hi) {
    asm("mov.b64 {%0, %1}, %2;" : "=f"(lo), "=f"(hi) : "l"(v));
}
__device__ __forceinline__ float hi2(u64 v) {
    float lo, hi; upk2(v, lo, hi); return hi;
}
__device__ __forceinline__ void ffma2(u64& d, u64 a, u64 b) {
    asm("fma.rn.f32x2 %0, %1, %2, %0;" : "+l"(d) : "l"(a), "l"(b));
}

// one 8-step MAC over both 8-output tiles: 2 LDS.128 noise, 64 ffma2
#define MAC(sb_, R_) do {                                                     \
    ulonglong2 nn0 = *(const ulonglong2*)(nrow + (sb_));                      \
    ulonglong2 nn1 = *(const ulonglong2*)(nrow + (sb_) + 4);                  \
    u64 nA[4] = {nn0.x, nn0.y, nn1.x, nn1.y};                                 \
    _Pragma("unroll") for (int u = 0; u < 4; ++u) {                           \
        _Pragma("unroll") for (int i = 0; i < 8; ++i)                         \
            ffma2(accA[i], nA[u], R_[i - 2*u + 6]);                           \
        _Pragma("unroll") for (int i = 0; i < 8; ++i)                         \
            ffma2(accB[i], nA[u], R_[i - 2*u + 14]);                          \
    }                                                                         \
} while (0)

// slide window 8 left (Rout[8..21] = Rin[0..13] by renaming), then MAC
#define BSTEP(Rin, Rout) do {                                                 \
    x -= 8;                                                                   \
    float4 La = *(const float4*)(hrow + x - 8);                               \
    float4 Lb = *(const float4*)(hrow + x - 4);                               \
    float L[8] = {La.x, La.y, La.z, La.w, Lb.x, Lb.y, Lb.z, Lb.w};            \
    _Pragma("unroll") for (int idx = 0; idx < 6; ++idx)                       \
        Rout[idx] = pk2(L[idx + 2], L[idx + 1]);                              \
    Rout[6] = pk2(h_top, L[7]);                                               \
    Rout[7] = pk2(hi2(Rin[0]), h_top);                                        \
    _Pragma("unroll") for (int idx = 8; idx < 22; ++idx)                      \
        Rout[idx] = Rin[idx - 8];                                             \
    h_top = L[0];                                                             \
    MAC(sb, Rout);                                                            \
    sb += 8;                                                                  \
} while (0)

__global__ __launch_bounds__(THREADS, 4)
void filtered_noise_kernel(const float* __restrict__ filt,
                           const float* __restrict__ noise,
                           float* __restrict__ out,
                           int F, long outlen)
{
    __shared__ __align__(16) float sX[36 * SXROW];   // scaled X (X0 pre-halved)
    __shared__ __align__(16) float sH[36 * SHROW];
    __shared__ __align__(16) float sN[34 * SNROW];   // n2 = 2*noise-1

    const int tid  = threadIdx.x;
    const int w    = tid >> 5;
    const int lane = tid & 31;
    const int g    = blockIdx.x;
    const int b    = blockIdx.y;
    const long base_f = (long)g * 32 - 2;

    const float* fb = filt  + (long)b * F * 65;
    const float* nb = noise + (long)b * F * 64;

    // ---- fills ----
    for (int i = tid; i < 36 * SXROW; i += THREADS) {
        int lf = i / SXROW, k = i - lf * SXROW;
        long f = base_f + lf;
        float v = 0.0f;
        if (lf < 34 && k < 65 && f >= 0 && f < F) v = fb[f * 65 + k];
        sX[i] = (k == 0) ? 0.5f * v : v;      // fold the k=0 half-weight
    }
    for (int i = tid; i < 34 * 16; i += THREADS) {
        int lf = i >> 4, j = i & 15;
        long f = base_f + lf;
        float4 v = make_float4(0.5f, 0.5f, 0.5f, 0.5f);
        if (f >= 0 && f < F) v = ((const float4*)(nb + f * 64))[j];
        *(float4*)(sN + lf * SNROW + 4 * j) =
            make_float4(2.0f * v.x - 1.0f, 2.0f * v.y - 1.0f,
                        2.0f * v.z - 1.0f, 2.0f * v.w - 1.0f);
    }
    for (int i = tid; i < 36 * 39; i += THREADS) {   // zero sH pads
        int lf = i / 39, j = i - lf * 39;
        sH[lf * SHROW + (j < 16 ? j : j + 129)] = 0.0f;
    }
    __syncthreads();

    // ---- Phase A: IR synthesis, 4 warps x 9 frames, float4 k-broadcasts ----
    {
        const int n0 = lane + 1, n1 = lane + 33;
        const float th0 = cospif((float)(2 * n0) / 129.0f);
        const float th1 = cospif((float)(2 * n1) / 129.0f);
        const float k20 = 2.0f * th0, k21 = 2.0f * th1;
        float c0 = 1.0f, c1 = 1.0f, p0 = th0, p1 = th1;   // cos(k t), cos((k-1)t)

        const int fs = 9 * w;                 // frames fs..fs+8 (rows 34,35: X=0)
        const float* xp = sX + fs * SXROW;
        u64 acc[9];
        #pragma unroll
        for (int j = 0; j < 9; ++j) acc[j] = 0ull;

        for (int k4 = 0; k4 < 17; ++k4) {     // k = 0..67 (65..67 are zero pads)
            float4 xv[9];
            #pragma unroll
            for (int j = 0; j < 9; ++j)
                xv[j] = *(const float4*)(xp + j * SXROW + 4 * k4);
            #pragma unroll
            for (int e = 0; e < 4; ++e) {
                u64 cc = pk2(c0, c1);
                #pragma unroll
                for (int j = 0; j < 9; ++j) {
                    float xe = (e == 0) ? xv[j].x : (e == 1) ? xv[j].y
                             : (e == 2) ? xv[j].z : xv[j].w;
                    ffma2(acc[j], pk2(xe, xe), cc);
                }
                float t0n = fmaf(k20, c0, -p0); p0 = c0; c0 = t0n;
                float t1n = fmaf(k21, c1, -p1); p1 = c1; c1 = t1n;
            }
        }
        const float S = 0.02f / 129.0f;       // GAIN * 2 / 129
        float w1a = (0.5f - 0.5f * cospif((float)(2 * (64 - n0)) / 129.0f)) * S;
        float w2a = (0.5f - 0.5f * cospif((float)(2 * (64 + n0)) / 129.0f)) * S;
        float w1b = (0.5f - 0.5f * cospif((float)(2 * (64 - n1)) / 129.0f)) * S;
        float w2b = (0.5f - 0.5f * cospif((float)(2 * (64 + n1)) / 129.0f)) * S;
        #pragma unroll
        for (int j = 0; j < 9; ++j) {
            float i0, i1; upk2(acc[j], i0, i1);
            float* hr = sH + (fs + j) * SHROW + HPAD;
            hr[64 - n0] = i0 * w1a;  hr[64 + n0] = i0 * w2a;
            hr[64 - n1] = i1 * w1b;  hr[64 + n1] = i1 * w2b;
        }
    }
    // n = 0 leftover: h[64] = win[64]*S * (0.5 X0 + sum_k Xk)   (X0 pre-halved)
    if (tid < 34) {
        const float* xr = sX + tid * SXROW;
        float s0 = xr[0], s1 = 0.0f, s2 = 0.0f, s3 = 0.0f;
        #pragma unroll 4
        for (int k = 1; k < 65; k += 4) {
            s0 += xr[k]; s1 += xr[k + 1]; s2 += xr[k + 2]; s3 += xr[k + 3];
        }
        const float win64s = (0.5f - 0.5f * cospif(128.0f / 129.0f)) * (0.02f / 129.0f);
        sH[tid * SHROW + HPAD + 64] = (s0 + s1 + s2 + s3) * win64s;
    }
    __syncthreads();

    // ---- Phase B: fused two-tile FIR conv + OLA ----
    const int tau = w << 4;        // 0,16,32,48
    const int hb  = lane;          // local hop block

    u64 accA[8], accB[8];          // tiles [tau, tau+8) and [tau+8, tau+16)
    #pragma unroll
    for (int i = 0; i < 8; ++i) { accA[i] = 0ull; accB[i] = 0ull; }

    #pragma unroll
    for (int d = 0; d < 3; ++d) {  // frame offset: f = hopblock - d
        long fglob = (long)g * 32 + hb - d;
        if (fglob < 0 || fglob >= F) continue;
        const int lf = hb - d + 2;
        const int t0 = tau + (d << 6);
        const int s_lo  = (d == 2) ? tau : 0;
        const int s_end = (d == 0) ? tau + 16 : 64;

        const float* hrow = sH + lf * SHROW + HPAD;   // hrow[-16..151] valid
        const float* nrow = sN + lf * SNROW;

        int x  = t0 - s_lo;        // multiple of 8
        int sb = s_lo;
        float h_top;
        u64 Ra[22], Rb[22];        // R[idx] = (h[m+1], h[m]), m = x-7+idx
        {   // prologue: build Ra for the first block, then MAC
            float hb24[24];        // h[x-8 .. x+15]
            #pragma unroll
            for (int q = 0; q < 6; ++q) {
                float4 t = *(const float4*)(hrow + x - 8 + 4 * q);
                hb24[4*q] = t.x; hb24[4*q+1] = t.y; hb24[4*q+2] = t.z; hb24[4*q+3] = t.w;
            }
            #pragma unroll
            for (int idx = 0; idx < 22; ++idx)
                Ra[idx] = pk2(hb24[idx + 2], hb24[idx + 1]);
            h_top = hb24[0];       // h[x-8] for the next slide
            MAC(sb, Ra);
            sb += 8;
        }
        while (sb + 15 < s_end) {  // even pairs: register-renamed R rotation
            BSTEP(Ra, Rb);
            BSTEP(Rb, Ra);
        }
        if (sb < s_end) {
            BSTEP(Ra, Rb);
        }
    }

    // each (g, hb, tau) tile of 16 samples owned by exactly one thread
    long p0 = (long)g * 2048 + (long)hb * 64 + tau;
    float* op = out + (long)b * outlen + p0;
    if (p0 < outlen) {
        float o[8];
        #pragma unroll
        for (int i = 0; i < 8; ++i) { float lo, hi; upk2(accA[i], lo, hi); o[i] = lo + hi; }
        reinterpret_cast<float4*>(op)[0] = make_float4(o[0], o[1], o[2], o[3]);
        reinterpret_cast<float4*>(op)[1] = make_float4(o[4], o[5], o[6], o[7]);
    }
    if (p0 + 8 < outlen) {
        float o[8];
        #pragma unroll
        for (int i = 0; i < 8; ++i) { float lo, hi; upk2(accB[i], lo, hi); o[i] = lo + hi; }
        reinterpret_cast<float4*>(op)[2] = make_float4(o[0], o[1], o[2], o[3]);
        reinterpret_cast<float4*>(op)[3] = make_float4(o[4], o[5], o[6], o[7]);
    }
}

extern "C" void kernel_launch(void* const* d_in, const int* in_sizes, int n_in,
                              void* d_out, int out_size)
{
    const float* d_filter = (const float*)d_in[0];   // [B, F, 65]
    const float* d_noise  = (const float*)d_in[1];   // [B, F, 64]
    float* d_o = (float*)d_out;                      // [B, (F-1)*64 + 192]

    const long nframes = (long)in_sizes[0] / 65;     // B*F
    const long B = ((long)out_size - 64 * nframes) / 128;
    const int  F = (int)(nframes / B);
    const long outlen = (long)(F - 1) * 64 + 192;
    const int  G = (int)((outlen + 2047) / 2048);

    dim3 grid((unsigned)G, (unsigned)B);
    filtered_noise_kernel<<<grid, THREADS>>>(d_filter, d_noise, d_o, F, outlen);
}